// round 2
// baseline (speedup 1.0000x reference)
#include <cuda_runtime.h>
#include <cuda_bf16.h>
#include <math.h>

// Problem constants
#define Bc   8
#define Tc   2048
#define Cc   512
#define Hc   8
#define Nc   64
#define DMIX 32
#define DDEC 64
#define BT   (Bc*Tc)           // 16384
#define BTC  (BT*Cc)           // 8388608

// ---------------------------------------------------------------------------
// Scratch (static device globals; no allocation allowed)
// ---------------------------------------------------------------------------
__device__ float g_xx  [BTC];
__device__ float g_xxx [BTC];
__device__ float g_h   [BT*160];
__device__ float g_xw  [BTC];
__device__ float g_xk  [BTC];
__device__ float g_xv  [BTC];
__device__ float g_xr  [BTC];
__device__ float g_xg  [BTC];
__device__ float g_r   [BTC];
__device__ float g_k   [BTC];
__device__ float g_v   [BTC];
__device__ float g_gate[BTC];
__device__ float g_wp  [BT*DDEC];
__device__ float g_w   [BTC];
__device__ float g_y   [BTC];
__device__ float g_z   [BTC];

// ---------------------------------------------------------------------------
// Elementwise: token shift + xxx = x + xx * maa_x
// ---------------------------------------------------------------------------
__global__ void ew_shift_mix(const float* __restrict__ x,
                             const float* __restrict__ maa_x,
                             float* __restrict__ xx, float* __restrict__ xxx)
{
    int idx = blockIdx.x * 256 + threadIdx.x;
    if (idx >= BTC) return;
    int c  = idx & (Cc - 1);
    int tg = idx >> 9;
    int tt = tg & (Tc - 1);
    float xi = x[idx];
    float xs = (tt > 0) ? x[idx - Cc] : 0.f;
    float xxv = xs - xi;
    xx[idx]  = xxv;
    xxx[idx] = fmaf(xxv, maa_x[c], xi);
}

// ---------------------------------------------------------------------------
// Generic tiled SGEMM: C[M,N] = epi( A[M,K] * B (+extras) )
//   TB=false: B is [K,N] row-major.  TB=true: B is [N,K] row-major (C = A*B^T)
//   EPI: 0 none, 1 tanh, 2 silu, 3 w_eff = exp(-exp(bias[n]+v)),
//        4 mix: out = xs + xxs * (bias[n] + v)   (xs/xxs same shape as C)
//   64x64 tile, BK=16, 256 threads, 4x4 per-thread microtile.
//   Requires: M % 64 == 0, K % 16 == 0 (N guarded).
// ---------------------------------------------------------------------------
template<bool TB, int EPI>
__global__ __launch_bounds__(256)
void sgemm_kernel(const float* __restrict__ A, const float* __restrict__ Bm,
                  float* __restrict__ Cm, const float* __restrict__ bias,
                  const float* __restrict__ xs, const float* __restrict__ xxs,
                  int M, int N, int K, int lda, int ldb, int ldc)
{
    __shared__ float As[16][68];
    __shared__ float Bs[16][68];

    int tid = threadIdx.x;
    int tx = tid & 15, ty = tid >> 4;
    int m0 = blockIdx.y * 64;
    int n0 = blockIdx.x * 64;
    bool fulln = (n0 + 64 <= N);

    float acc[4][4];
#pragma unroll
    for (int i = 0; i < 4; i++)
#pragma unroll
        for (int j = 0; j < 4; j++) acc[i][j] = 0.f;

    for (int k0 = 0; k0 < K; k0 += 16) {
        // --- A tile: As[k][m] ---
        {
            int row = tid >> 2, kq = tid & 3;
            const float4 av = *reinterpret_cast<const float4*>(
                &A[(size_t)(m0 + row) * lda + k0 + kq * 4]);
            As[kq * 4 + 0][row] = av.x;
            As[kq * 4 + 1][row] = av.y;
            As[kq * 4 + 2][row] = av.z;
            As[kq * 4 + 3][row] = av.w;
        }
        // --- B tile: Bs[k][n] ---
        if (!TB) {
            int kr = tid >> 4, nq = tid & 15;
            int n = n0 + nq * 4;
            if (fulln) {
                float4 bv = *reinterpret_cast<const float4*>(
                    &Bm[(size_t)(k0 + kr) * ldb + n]);
                *reinterpret_cast<float4*>(&Bs[kr][nq * 4]) = bv;
            } else {
                float4 bv;
                bv.x = (n + 0 < N) ? Bm[(size_t)(k0 + kr) * ldb + n + 0] : 0.f;
                bv.y = (n + 1 < N) ? Bm[(size_t)(k0 + kr) * ldb + n + 1] : 0.f;
                bv.z = (n + 2 < N) ? Bm[(size_t)(k0 + kr) * ldb + n + 2] : 0.f;
                bv.w = (n + 3 < N) ? Bm[(size_t)(k0 + kr) * ldb + n + 3] : 0.f;
                *reinterpret_cast<float4*>(&Bs[kr][nq * 4]) = bv;
            }
        } else {
            int nrow = tid >> 2, kq = tid & 3;
            int n = n0 + nrow;
            float4 bv = make_float4(0.f, 0.f, 0.f, 0.f);
            if (n < N)
                bv = *reinterpret_cast<const float4*>(
                    &Bm[(size_t)n * ldb + k0 + kq * 4]);
            Bs[kq * 4 + 0][nrow] = bv.x;
            Bs[kq * 4 + 1][nrow] = bv.y;
            Bs[kq * 4 + 2][nrow] = bv.z;
            Bs[kq * 4 + 3][nrow] = bv.w;
        }
        __syncthreads();

#pragma unroll
        for (int kk = 0; kk < 16; kk++) {
            float4 a4 = *reinterpret_cast<const float4*>(&As[kk][ty * 4]);
            float4 b4 = *reinterpret_cast<const float4*>(&Bs[kk][tx * 4]);
            float ar[4] = {a4.x, a4.y, a4.z, a4.w};
            float br[4] = {b4.x, b4.y, b4.z, b4.w};
#pragma unroll
            for (int i = 0; i < 4; i++)
#pragma unroll
                for (int j = 0; j < 4; j++)
                    acc[i][j] = fmaf(ar[i], br[j], acc[i][j]);
        }
        __syncthreads();
    }

#pragma unroll
    for (int i = 0; i < 4; i++) {
        int m = m0 + ty * 4 + i;
#pragma unroll
        for (int j = 0; j < 4; j++) {
            int n = n0 + tx * 4 + j;
            if (n < N) {
                float v = acc[i][j];
                size_t oidx = (size_t)m * ldc + n;
                if (EPI == 1) v = tanhf(v);
                else if (EPI == 2) v = v / (1.f + expf(-v));
                else if (EPI == 3) v = expf(-expf(bias[n] + v));
                else if (EPI == 4) v = fmaf(xxs[oidx], bias[n] + v, xs[oidx]);
                Cm[oidx] = v;
            }
        }
    }
}

// ---------------------------------------------------------------------------
// WKV6 linear recurrence.
// grid = 128 blocks: block -> (b, h, i-half). 128 threads = 4 warps.
// Warp jq owns state rows j in [jq*16, jq*16+16); lane = local output index i.
// S[j][i] in registers (16 per thread).
// ---------------------------------------------------------------------------
__global__ __launch_bounds__(128)
void wkv_kernel(const float* __restrict__ r, const float* __restrict__ k,
                const float* __restrict__ v, const float* __restrict__ w,
                const float* __restrict__ u, float* __restrict__ y)
{
    int bid  = blockIdx.x;
    int ih   = bid & 1;
    int h    = (bid >> 1) & 7;
    int b    = bid >> 4;
    int tid  = threadIdx.x;
    int lane = tid & 31;
    int warp = tid >> 5;          // = jq

    __shared__ float sr[64], sk[64], sw[64], sv[32];
    __shared__ float part[4][32];

    float S[16];
#pragma unroll
    for (int jj = 0; jj < 16; jj++) S[jj] = 0.f;

    float uu[16];
#pragma unroll
    for (int jj = 0; jj < 16; jj++) uu[jj] = u[h * 64 + warp * 16 + jj];

    int hbase = h * 64;
    for (int t = 0; t < Tc; t++) {
        size_t base = (size_t)(b * Tc + t) * Cc + hbase;
        if (tid < 64) {
            sr[tid] = r[base + tid];
            sk[tid] = k[base + tid];
        } else {
            int j = tid - 64;
            sw[j] = w[base + j];
            if (j < 32) sv[j] = v[base + ih * 32 + j];
        }
        __syncthreads();

        float vi = sv[lane];
        float y0 = 0.f, y1 = 0.f;
#pragma unroll
        for (int jj = 0; jj < 16; jj++) {
            int j = warp * 16 + jj;
            float kv  = sk[j] * vi;
            float acc = fmaf(uu[jj], kv, S[jj]);
            if (jj & 1) y1 = fmaf(sr[j], acc, y1);
            else        y0 = fmaf(sr[j], acc, y0);
            S[jj] = fmaf(sw[j], S[jj], kv);
        }
        part[warp][lane] = y0 + y1;
        __syncthreads();

        if (tid < 32) {
            float yv = part[0][tid] + part[1][tid] + part[2][tid] + part[3][tid];
            y[base + ih * 32 + tid] = yv;
        }
        // next iteration's staging is gated by the first __syncthreads
    }
}

// ---------------------------------------------------------------------------
// GroupNorm (H groups of N=64) + ln scale/shift + gate multiply
// one warp per (b,t,h) group
// ---------------------------------------------------------------------------
__global__ __launch_bounds__(256)
void gn_kernel(const float* __restrict__ y, const float* __restrict__ gsrc,
               const float* __restrict__ lng, const float* __restrict__ lnb,
               float* __restrict__ z)
{
    int warp = threadIdx.x >> 5, lane = threadIdx.x & 31;
    int grp = blockIdx.x * 8 + warp;           // < BT*H
    int tg = grp >> 3, h = grp & 7;
    size_t base = (size_t)tg * Cc + h * 64;

    float y0 = y[base + lane];
    float y1 = y[base + 32 + lane];
    float s  = y0 + y1;
    float ss = y0 * y0 + y1 * y1;
#pragma unroll
    for (int o = 16; o; o >>= 1) {
        s  += __shfl_xor_sync(0xffffffffu, s, o);
        ss += __shfl_xor_sync(0xffffffffu, ss, o);
    }
    float mean = s * (1.f / 64.f);
    float var  = ss * (1.f / 64.f) - mean * mean;
    float rstd = rsqrtf(var + 1e-5f);

    int c0 = h * 64 + lane;
    float z0 = fmaf((y0 - mean) * rstd, lng[c0],      lnb[c0]);
    float z1 = fmaf((y1 - mean) * rstd, lng[c0 + 32], lnb[c0 + 32]);
    z[base + lane]      = z0 * gsrc[base + lane];
    z[base + 32 + lane] = z1 * gsrc[base + 32 + lane];
}

// ---------------------------------------------------------------------------
// Launch
// ---------------------------------------------------------------------------
template <typename T>
static float* devptr(T& sym)
{
    void* p = nullptr;
    cudaGetSymbolAddress(&p, sym);
    return (float*)p;
}

extern "C" void kernel_launch(void* const* d_in, const int* in_sizes, int n_in,
                              void* d_out, int out_size)
{
    const float* x      = (const float*)d_in[0];
    const float* maa_x  = (const float*)d_in[1];
    const float* maa_w  = (const float*)d_in[2];
    const float* maa_k  = (const float*)d_in[3];
    const float* maa_v  = (const float*)d_in[4];
    const float* maa_r  = (const float*)d_in[5];
    const float* maa_g  = (const float*)d_in[6];
    const float* W1     = (const float*)d_in[7];   // [512,160]
    const float* W2     = (const float*)d_in[8];   // [5,32,512]
    const float* tdec   = (const float*)d_in[9];   // [512]
    const float* dw1    = (const float*)d_in[10];  // [512,64]
    const float* dw2    = (const float*)d_in[11];  // [64,512]
    const float* faaaa  = (const float*)d_in[12];  // [8,64]
    const float* Wr     = (const float*)d_in[13];
    const float* Wk     = (const float*)d_in[14];
    const float* Wv     = (const float*)d_in[15];
    const float* Wg     = (const float*)d_in[16];
    const float* Wo     = (const float*)d_in[17];
    const float* ln_g   = (const float*)d_in[18];
    const float* ln_b   = (const float*)d_in[19];
    float* out = (float*)d_out;

    float* p_xx   = devptr(g_xx);
    float* p_xxx  = devptr(g_xxx);
    float* p_h    = devptr(g_h);
    float* p_xw   = devptr(g_xw);
    float* p_xk   = devptr(g_xk);
    float* p_xv   = devptr(g_xv);
    float* p_xr   = devptr(g_xr);
    float* p_xg   = devptr(g_xg);
    float* p_r    = devptr(g_r);
    float* p_k    = devptr(g_k);
    float* p_v    = devptr(g_v);
    float* p_gate = devptr(g_gate);
    float* p_wp   = devptr(g_wp);
    float* p_w    = devptr(g_w);
    float* p_y    = devptr(g_y);
    float* p_z    = devptr(g_z);

    const int ewGrid = (BTC + 255) / 256;

    // 1) token shift + xxx
    ew_shift_mix<<<ewGrid, 256>>>(x, maa_x, p_xx, p_xxx);

    // 2) h = tanh(xxx @ W1)   [16384,160]
    {
        dim3 grid((160 + 63) / 64, BT / 64);
        sgemm_kernel<false, 1><<<grid, 256>>>(p_xxx, W1, p_h, nullptr, nullptr, nullptr,
                                              BT, 160, Cc, Cc, 160, 160);
    }
    // 3+4) fused: x_f = x + xx*(maa_f + h[:,f] @ W2[f]) for f in {w,k,v,r,g}
    {
        dim3 grid(Cc / 64, BT / 64);
        const float* maas[5] = {maa_w, maa_k, maa_v, maa_r, maa_g};
        float* outs[5] = {p_xw, p_xk, p_xv, p_xr, p_xg};
        for (int f = 0; f < 5; f++) {
            sgemm_kernel<false, 4><<<grid, 256>>>(p_h + f * 32, W2 + (size_t)f * 32 * Cc,
                                                  outs[f], maas[f], x, p_xx,
                                                  BT, Cc, 32, 160, Cc, Cc);
        }
    }

    // 5) projections r, k, v (C = A * W^T)
    {
        dim3 grid(Cc / 64, BT / 64);
        sgemm_kernel<true, 0><<<grid, 256>>>(p_xr, Wr, p_r, nullptr, nullptr, nullptr,
                                             BT, Cc, Cc, Cc, Cc, Cc);
        sgemm_kernel<true, 0><<<grid, 256>>>(p_xk, Wk, p_k, nullptr, nullptr, nullptr,
                                             BT, Cc, Cc, Cc, Cc, Cc);
        sgemm_kernel<true, 0><<<grid, 256>>>(p_xv, Wv, p_v, nullptr, nullptr, nullptr,
                                             BT, Cc, Cc, Cc, Cc, Cc);
        // gate with silu
        sgemm_kernel<true, 2><<<grid, 256>>>(p_xg, Wg, p_gate, nullptr, nullptr, nullptr,
                                             BT, Cc, Cc, Cc, Cc, Cc);
    }
    // 6) decay path: wp = tanh(xw @ dw1); w_eff = exp(-exp(tdec + wp @ dw2))
    {
        dim3 grid1(1, BT / 64);
        sgemm_kernel<false, 1><<<grid1, 256>>>(p_xw, dw1, p_wp, nullptr, nullptr, nullptr,
                                               BT, DDEC, Cc, Cc, DDEC, DDEC);
        dim3 grid2(Cc / 64, BT / 64);
        sgemm_kernel<false, 3><<<grid2, 256>>>(p_wp, dw2, p_w, tdec, nullptr, nullptr,
                                               BT, Cc, DDEC, DDEC, Cc, Cc);
    }

    // 7) WKV6 recurrence
    wkv_kernel<<<Bc * Hc * 2, 128>>>(p_r, p_k, p_v, p_w, faaaa, p_y);

    // 8) GroupNorm + gate
    gn_kernel<<<(BT * Hc) / 8, 256>>>(p_y, p_gate, ln_g, ln_b, p_z);

    // 9) out = z @ Wo^T
    {
        dim3 grid(Cc / 64, BT / 64);
        sgemm_kernel<true, 0><<<grid, 256>>>(p_z, Wo, out, nullptr, nullptr, nullptr,
                                             BT, Cc, Cc, Cc, Cc, Cc);
    }
}

// round 3
// speedup vs baseline: 1.4700x; 1.4700x over previous
#include <cuda_runtime.h>
#include <cuda_bf16.h>
#include <math.h>
#include <stdint.h>

// Problem constants
#define Bc   8
#define Tc   2048
#define Cc   512
#define Hc   8
#define Nc   64
#define DMIX 32
#define DDEC 64
#define BT   (Bc*Tc)           // 16384
#define BTC  (BT*Cc)           // 8388608

// ---------------------------------------------------------------------------
// Scratch (static device globals; no allocation allowed)
// ---------------------------------------------------------------------------
__device__ float g_xx  [BTC];
__device__ float g_xxx [BTC];
__device__ float g_h   [BT*160];
__device__ float g_xw  [BTC];
__device__ float g_xk  [BTC];
__device__ float g_xv  [BTC];
__device__ float g_xr  [BTC];
__device__ float g_xg  [BTC];
__device__ float g_r   [BTC];
__device__ float g_k   [BTC];
__device__ float g_v   [BTC];
__device__ float g_gate[BTC];
__device__ float g_wp  [BT*DDEC];
__device__ float g_w   [BTC];
__device__ float g_y   [BTC];
__device__ float g_z   [BTC];

// ---------------------------------------------------------------------------
// Elementwise: token shift + xxx = x + xx * maa_x
// ---------------------------------------------------------------------------
__global__ void ew_shift_mix(const float* __restrict__ x,
                             const float* __restrict__ maa_x,
                             float* __restrict__ xx, float* __restrict__ xxx)
{
    int idx = blockIdx.x * 256 + threadIdx.x;
    if (idx >= BTC) return;
    int c  = idx & (Cc - 1);
    int tg = idx >> 9;
    int tt = tg & (Tc - 1);
    float xi = x[idx];
    float xs = (tt > 0) ? x[idx - Cc] : 0.f;
    float xxv = xs - xi;
    xx[idx]  = xxv;
    xxx[idx] = fmaf(xxv, maa_x[c], xi);
}

// ---------------------------------------------------------------------------
// TF32 tensor-core GEMM (mma.sync.m16n8k8):
//   C[M,N] = epi( A[M,K] @ W[N,K]^T )
//   Requires M%128==0, N%128==0, K%16==0.  EPI: 0 none, 2 silu.
//   128x128 block tile, BK=16, 256 threads (8 warps, 64x32 warp tiles),
//   double-buffered smem, stride-20 padding (conflict-free fragment loads).
// ---------------------------------------------------------------------------
__device__ __forceinline__ uint32_t f2tf32(float x)
{
    uint32_t u;
    asm("cvt.rna.tf32.f32 %0, %1;" : "=r"(u) : "f"(x));
    return u;
}

template<int EPI>
__global__ __launch_bounds__(256)
void tf32_gemm_tb(const float* __restrict__ A, const float* __restrict__ W,
                  float* __restrict__ Cm, int M, int N, int K)
{
    __shared__ float As[2][128][20];
    __shared__ float Bs[2][128][20];

    int tid  = threadIdx.x;
    int warp = tid >> 5, lane = tid & 31;
    int wm = (warp >> 2) * 64;     // 0 or 64
    int wn = (warp & 3) * 32;      // 0,32,64,96
    int gid = lane >> 2, tig = lane & 3;
    int m0 = blockIdx.y * 128, n0 = blockIdx.x * 128;

    // gmem staging mapping: thread -> (row in tile, two float4 quads)
    int lr = tid >> 1;             // 0..127
    int lq = (tid & 1) * 2;        // quad base 0 or 2
    const float* Aptr = A + (size_t)(m0 + lr) * K;
    const float* Wptr = W + (size_t)(n0 + lr) * K;

    float acc[4][4][4];
#pragma unroll
    for (int mt = 0; mt < 4; mt++)
#pragma unroll
        for (int nt = 0; nt < 4; nt++)
#pragma unroll
            for (int d = 0; d < 4; d++) acc[mt][nt][d] = 0.f;

    auto stage = [&](int buf, int k0) {
#pragma unroll
        for (int i = 0; i < 2; i++) {
            int kq = (lq + i) * 4;
            float4 av = *reinterpret_cast<const float4*>(Aptr + k0 + kq);
            av.x = __uint_as_float(f2tf32(av.x));
            av.y = __uint_as_float(f2tf32(av.y));
            av.z = __uint_as_float(f2tf32(av.z));
            av.w = __uint_as_float(f2tf32(av.w));
            *reinterpret_cast<float4*>(&As[buf][lr][kq]) = av;
            float4 bv = *reinterpret_cast<const float4*>(Wptr + k0 + kq);
            bv.x = __uint_as_float(f2tf32(bv.x));
            bv.y = __uint_as_float(f2tf32(bv.y));
            bv.z = __uint_as_float(f2tf32(bv.z));
            bv.w = __uint_as_float(f2tf32(bv.w));
            *reinterpret_cast<float4*>(&Bs[buf][lr][kq]) = bv;
        }
    };

    stage(0, 0);
    __syncthreads();

    for (int k0 = 0; k0 < K; k0 += 16) {
        int buf = (k0 >> 4) & 1;
        if (k0 + 16 < K) stage(buf ^ 1, k0 + 16);

#pragma unroll
        for (int ks = 0; ks < 2; ks++) {
            int kb = ks * 8;
            uint32_t afr[4][4];
#pragma unroll
            for (int mt = 0; mt < 4; mt++) {
                int m = wm + mt * 16;
                afr[mt][0] = __float_as_uint(As[buf][m + gid    ][kb + tig    ]);
                afr[mt][1] = __float_as_uint(As[buf][m + gid + 8][kb + tig    ]);
                afr[mt][2] = __float_as_uint(As[buf][m + gid    ][kb + tig + 4]);
                afr[mt][3] = __float_as_uint(As[buf][m + gid + 8][kb + tig + 4]);
            }
            uint32_t bfr[4][2];
#pragma unroll
            for (int nt = 0; nt < 4; nt++) {
                int n = wn + nt * 8;
                bfr[nt][0] = __float_as_uint(Bs[buf][n + gid][kb + tig    ]);
                bfr[nt][1] = __float_as_uint(Bs[buf][n + gid][kb + tig + 4]);
            }
#pragma unroll
            for (int mt = 0; mt < 4; mt++)
#pragma unroll
                for (int nt = 0; nt < 4; nt++) {
                    asm volatile(
                        "mma.sync.aligned.m16n8k8.row.col.f32.tf32.tf32.f32 "
                        "{%0,%1,%2,%3}, {%4,%5,%6,%7}, {%8,%9}, {%0,%1,%2,%3};"
                        : "+f"(acc[mt][nt][0]), "+f"(acc[mt][nt][1]),
                          "+f"(acc[mt][nt][2]), "+f"(acc[mt][nt][3])
                        : "r"(afr[mt][0]), "r"(afr[mt][1]),
                          "r"(afr[mt][2]), "r"(afr[mt][3]),
                          "r"(bfr[nt][0]), "r"(bfr[nt][1]));
                }
        }
        __syncthreads();
    }

    // epilogue
#pragma unroll
    for (int mt = 0; mt < 4; mt++) {
        int m = m0 + wm + mt * 16 + gid;
#pragma unroll
        for (int nt = 0; nt < 4; nt++) {
            int n = n0 + wn + nt * 8 + 2 * tig;
            float v0 = acc[mt][nt][0], v1 = acc[mt][nt][1];
            float v2 = acc[mt][nt][2], v3 = acc[mt][nt][3];
            if (EPI == 2) {
                v0 = v0 / (1.f + expf(-v0));
                v1 = v1 / (1.f + expf(-v1));
                v2 = v2 / (1.f + expf(-v2));
                v3 = v3 / (1.f + expf(-v3));
            }
            *reinterpret_cast<float2*>(&Cm[(size_t)m * N + n])       = make_float2(v0, v1);
            *reinterpret_cast<float2*>(&Cm[(size_t)(m + 8) * N + n]) = make_float2(v2, v3);
        }
    }
}

// ---------------------------------------------------------------------------
// Generic tiled SGEMM (SIMT) for the small GEMMs.
//   TB=false: B is [K,N] row-major.  TB=true: B is [N,K] row-major (C = A*B^T)
//   EPI: 0 none, 1 tanh, 2 silu, 3 w_eff = exp(-exp(bias[n]+v)),
//        4 mix: out = xs + xxs * (bias[n] + v)
// ---------------------------------------------------------------------------
template<bool TB, int EPI>
__global__ __launch_bounds__(256)
void sgemm_kernel(const float* __restrict__ A, const float* __restrict__ Bm,
                  float* __restrict__ Cm, const float* __restrict__ bias,
                  const float* __restrict__ xs, const float* __restrict__ xxs,
                  int M, int N, int K, int lda, int ldb, int ldc)
{
    __shared__ float As[16][68];
    __shared__ float Bs[16][68];

    int tid = threadIdx.x;
    int tx = tid & 15, ty = tid >> 4;
    int m0 = blockIdx.y * 64;
    int n0 = blockIdx.x * 64;
    bool fulln = (n0 + 64 <= N);

    float acc[4][4];
#pragma unroll
    for (int i = 0; i < 4; i++)
#pragma unroll
        for (int j = 0; j < 4; j++) acc[i][j] = 0.f;

    for (int k0 = 0; k0 < K; k0 += 16) {
        {
            int row = tid >> 2, kq = tid & 3;
            const float4 av = *reinterpret_cast<const float4*>(
                &A[(size_t)(m0 + row) * lda + k0 + kq * 4]);
            As[kq * 4 + 0][row] = av.x;
            As[kq * 4 + 1][row] = av.y;
            As[kq * 4 + 2][row] = av.z;
            As[kq * 4 + 3][row] = av.w;
        }
        if (!TB) {
            int kr = tid >> 4, nq = tid & 15;
            int n = n0 + nq * 4;
            if (fulln) {
                float4 bv = *reinterpret_cast<const float4*>(
                    &Bm[(size_t)(k0 + kr) * ldb + n]);
                *reinterpret_cast<float4*>(&Bs[kr][nq * 4]) = bv;
            } else {
                float4 bv;
                bv.x = (n + 0 < N) ? Bm[(size_t)(k0 + kr) * ldb + n + 0] : 0.f;
                bv.y = (n + 1 < N) ? Bm[(size_t)(k0 + kr) * ldb + n + 1] : 0.f;
                bv.z = (n + 2 < N) ? Bm[(size_t)(k0 + kr) * ldb + n + 2] : 0.f;
                bv.w = (n + 3 < N) ? Bm[(size_t)(k0 + kr) * ldb + n + 3] : 0.f;
                *reinterpret_cast<float4*>(&Bs[kr][nq * 4]) = bv;
            }
        } else {
            int nrow = tid >> 2, kq = tid & 3;
            int n = n0 + nrow;
            float4 bv = make_float4(0.f, 0.f, 0.f, 0.f);
            if (n < N)
                bv = *reinterpret_cast<const float4*>(
                    &Bm[(size_t)n * ldb + k0 + kq * 4]);
            Bs[kq * 4 + 0][nrow] = bv.x;
            Bs[kq * 4 + 1][nrow] = bv.y;
            Bs[kq * 4 + 2][nrow] = bv.z;
            Bs[kq * 4 + 3][nrow] = bv.w;
        }
        __syncthreads();

#pragma unroll
        for (int kk = 0; kk < 16; kk++) {
            float4 a4 = *reinterpret_cast<const float4*>(&As[kk][ty * 4]);
            float4 b4 = *reinterpret_cast<const float4*>(&Bs[kk][tx * 4]);
            float ar[4] = {a4.x, a4.y, a4.z, a4.w};
            float br[4] = {b4.x, b4.y, b4.z, b4.w};
#pragma unroll
            for (int i = 0; i < 4; i++)
#pragma unroll
                for (int j = 0; j < 4; j++)
                    acc[i][j] = fmaf(ar[i], br[j], acc[i][j]);
        }
        __syncthreads();
    }

#pragma unroll
    for (int i = 0; i < 4; i++) {
        int m = m0 + ty * 4 + i;
#pragma unroll
        for (int j = 0; j < 4; j++) {
            int n = n0 + tx * 4 + j;
            if (n < N) {
                float v = acc[i][j];
                size_t oidx = (size_t)m * ldc + n;
                if (EPI == 1) v = tanhf(v);
                else if (EPI == 2) v = v / (1.f + expf(-v));
                else if (EPI == 3) v = expf(-expf(bias[n] + v));
                else if (EPI == 4) v = fmaf(xxs[oidx], bias[n] + v, xs[oidx]);
                Cm[oidx] = v;
            }
        }
    }
}

// ---------------------------------------------------------------------------
// WKV6 linear recurrence with next-step prefetch.
// grid = 128 blocks: block -> (b, h, i-half). 128 threads = 4 warps.
// ---------------------------------------------------------------------------
__global__ __launch_bounds__(128)
void wkv_kernel(const float* __restrict__ r, const float* __restrict__ k,
                const float* __restrict__ v, const float* __restrict__ w,
                const float* __restrict__ u, float* __restrict__ y)
{
    int bid  = blockIdx.x;
    int ih   = bid & 1;
    int h    = (bid >> 1) & 7;
    int b    = bid >> 4;
    int tid  = threadIdx.x;
    int lane = tid & 31;
    int warp = tid >> 5;
    int j64  = tid - 64;

    __shared__ float sr[64], sk[64], sw[64], sv[32];
    __shared__ float part[4][32];

    float S[16];
#pragma unroll
    for (int jj = 0; jj < 16; jj++) S[jj] = 0.f;

    float uu[16];
#pragma unroll
    for (int jj = 0; jj < 16; jj++) uu[jj] = u[h * 64 + warp * 16 + jj];

    int hbase = h * 64;
    size_t base = (size_t)(b * Tc) * Cc + hbase;

    // prefetch t=0
    float pa = 0.f, pb = 0.f;
    if (tid < 64) { pa = r[base + tid]; pb = k[base + tid]; }
    else          { pa = w[base + j64]; if (j64 < 32) pb = v[base + ih * 32 + j64]; }

    for (int t = 0; t < Tc; t++) {
        // stage current
        if (tid < 64) { sr[tid] = pa; sk[tid] = pb; }
        else          { sw[j64] = pa; if (j64 < 32) sv[j64] = pb; }
        __syncthreads();

        // prefetch next while computing current
        if (t + 1 < Tc) {
            size_t nb = base + Cc;
            if (tid < 64) { pa = r[nb + tid]; pb = k[nb + tid]; }
            else          { pa = w[nb + j64]; if (j64 < 32) pb = v[nb + ih * 32 + j64]; }
        }

        float vi = sv[lane];
        float y0 = 0.f, y1 = 0.f;
#pragma unroll
        for (int jj = 0; jj < 16; jj++) {
            int j = warp * 16 + jj;
            float kv  = sk[j] * vi;
            float acc = fmaf(uu[jj], kv, S[jj]);
            if (jj & 1) y1 = fmaf(sr[j], acc, y1);
            else        y0 = fmaf(sr[j], acc, y0);
            S[jj] = fmaf(sw[j], S[jj], kv);
        }
        part[warp][lane] = y0 + y1;
        __syncthreads();

        if (tid < 32) {
            float yv = part[0][tid] + part[1][tid] + part[2][tid] + part[3][tid];
            y[base + ih * 32 + tid] = yv;
        }
        base += Cc;
    }
}

// ---------------------------------------------------------------------------
// GroupNorm (H groups of N=64) + ln scale/shift + gate multiply
// ---------------------------------------------------------------------------
__global__ __launch_bounds__(256)
void gn_kernel(const float* __restrict__ y, const float* __restrict__ gsrc,
               const float* __restrict__ lng, const float* __restrict__ lnb,
               float* __restrict__ z)
{
    int warp = threadIdx.x >> 5, lane = threadIdx.x & 31;
    int grp = blockIdx.x * 8 + warp;           // < BT*H
    int tg = grp >> 3, h = grp & 7;
    size_t base = (size_t)tg * Cc + h * 64;

    float y0 = y[base + lane];
    float y1 = y[base + 32 + lane];
    float s  = y0 + y1;
    float ss = y0 * y0 + y1 * y1;
#pragma unroll
    for (int o = 16; o; o >>= 1) {
        s  += __shfl_xor_sync(0xffffffffu, s, o);
        ss += __shfl_xor_sync(0xffffffffu, ss, o);
    }
    float mean = s * (1.f / 64.f);
    float var  = ss * (1.f / 64.f) - mean * mean;
    float rstd = rsqrtf(var + 1e-5f);

    int c0 = h * 64 + lane;
    float z0 = fmaf((y0 - mean) * rstd, lng[c0],      lnb[c0]);
    float z1 = fmaf((y1 - mean) * rstd, lng[c0 + 32], lnb[c0 + 32]);
    z[base + lane]      = z0 * gsrc[base + lane];
    z[base + 32 + lane] = z1 * gsrc[base + 32 + lane];
}

// ---------------------------------------------------------------------------
// Launch
// ---------------------------------------------------------------------------
template <typename T>
static float* devptr(T& sym)
{
    void* p = nullptr;
    cudaGetSymbolAddress(&p, sym);
    return (float*)p;
}

extern "C" void kernel_launch(void* const* d_in, const int* in_sizes, int n_in,
                              void* d_out, int out_size)
{
    const float* x      = (const float*)d_in[0];
    const float* maa_x  = (const float*)d_in[1];
    const float* maa_w  = (const float*)d_in[2];
    const float* maa_k  = (const float*)d_in[3];
    const float* maa_v  = (const float*)d_in[4];
    const float* maa_r  = (const float*)d_in[5];
    const float* maa_g  = (const float*)d_in[6];
    const float* W1     = (const float*)d_in[7];   // [512,160]
    const float* W2     = (const float*)d_in[8];   // [5,32,512]
    const float* tdec   = (const float*)d_in[9];   // [512]
    const float* dw1    = (const float*)d_in[10];  // [512,64]
    const float* dw2    = (const float*)d_in[11];  // [64,512]
    const float* faaaa  = (const float*)d_in[12];  // [8,64]
    const float* Wr     = (const float*)d_in[13];
    const float* Wk     = (const float*)d_in[14];
    const float* Wv     = (const float*)d_in[15];
    const float* Wg     = (const float*)d_in[16];
    const float* Wo     = (const float*)d_in[17];
    const float* ln_g   = (const float*)d_in[18];
    const float* ln_b   = (const float*)d_in[19];
    float* out = (float*)d_out;

    float* p_xx   = devptr(g_xx);
    float* p_xxx  = devptr(g_xxx);
    float* p_h    = devptr(g_h);
    float* p_xw   = devptr(g_xw);
    float* p_xk   = devptr(g_xk);
    float* p_xv   = devptr(g_xv);
    float* p_xr   = devptr(g_xr);
    float* p_xg   = devptr(g_xg);
    float* p_r    = devptr(g_r);
    float* p_k    = devptr(g_k);
    float* p_v    = devptr(g_v);
    float* p_gate = devptr(g_gate);
    float* p_wp   = devptr(g_wp);
    float* p_w    = devptr(g_w);
    float* p_y    = devptr(g_y);
    float* p_z    = devptr(g_z);

    const int ewGrid = (BTC + 255) / 256;

    // 1) token shift + xxx
    ew_shift_mix<<<ewGrid, 256>>>(x, maa_x, p_xx, p_xxx);

    // 2) h = tanh(xxx @ W1)   [16384,160]  (SIMT)
    {
        dim3 grid((160 + 63) / 64, BT / 64);
        sgemm_kernel<false, 1><<<grid, 256>>>(p_xxx, W1, p_h, nullptr, nullptr, nullptr,
                                              BT, 160, Cc, Cc, 160, 160);
    }
    // 3+4) fused: x_f = x + xx*(maa_f + h[:,f] @ W2[f]) for f in {w,k,v,r,g}
    {
        dim3 grid(Cc / 64, BT / 64);
        const float* maas[5] = {maa_w, maa_k, maa_v, maa_r, maa_g};
        float* outs[5] = {p_xw, p_xk, p_xv, p_xr, p_xg};
        for (int f = 0; f < 5; f++) {
            sgemm_kernel<false, 4><<<grid, 256>>>(p_h + f * 32, W2 + (size_t)f * 32 * Cc,
                                                  outs[f], maas[f], x, p_xx,
                                                  BT, Cc, 32, 160, Cc, Cc);
        }
    }

    // 5) projections r, k, v, g  (tensor-core tf32)
    {
        dim3 grid(Cc / 128, BT / 128);   // (4, 128)
        tf32_gemm_tb<0><<<grid, 256>>>(p_xr, Wr, p_r,    BT, Cc, Cc);
        tf32_gemm_tb<0><<<grid, 256>>>(p_xk, Wk, p_k,    BT, Cc, Cc);
        tf32_gemm_tb<0><<<grid, 256>>>(p_xv, Wv, p_v,    BT, Cc, Cc);
        tf32_gemm_tb<2><<<grid, 256>>>(p_xg, Wg, p_gate, BT, Cc, Cc);
    }
    // 6) decay path: wp = tanh(xw @ dw1); w_eff = exp(-exp(tdec + wp @ dw2)) (SIMT)
    {
        dim3 grid1(1, BT / 64);
        sgemm_kernel<false, 1><<<grid1, 256>>>(p_xw, dw1, p_wp, nullptr, nullptr, nullptr,
                                               BT, DDEC, Cc, Cc, DDEC, DDEC);
        dim3 grid2(Cc / 64, BT / 64);
        sgemm_kernel<false, 3><<<grid2, 256>>>(p_wp, dw2, p_w, tdec, nullptr, nullptr,
                                               BT, Cc, DDEC, DDEC, Cc, Cc);
    }

    // 7) WKV6 recurrence
    wkv_kernel<<<Bc * Hc * 2, 128>>>(p_r, p_k, p_v, p_w, faaaa, p_y);

    // 8) GroupNorm + gate
    gn_kernel<<<(BT * Hc) / 8, 256>>>(p_y, p_gate, ln_g, ln_b, p_z);

    // 9) out = z @ Wo^T  (tensor-core tf32)
    {
        dim3 grid(Cc / 128, BT / 128);
        tf32_gemm_tb<0><<<grid, 256>>>(p_z, Wo, out, BT, Cc, Cc);
    }
}